// round 12
// baseline (speedup 1.0000x reference)
#include <cuda_runtime.h>
#include <cuda_bf16.h>
#include <math.h>
#include <stdint.h>

#define B_  2
#define N_  2048
#define C_  1024
#define H_  16
#define HD_ 64
#define M_  (B_ * N_)      // 4096
#define QKVN (3 * C_)      // 3072
#define LOG2E 1.4426950408889634f

// ---------------- scratch ----------------
// staged layouts: 16KB GEMM blocks = [hi 8K][lo 8K], rows of 64B, SW64 swizzle
//                 32KB attn blocks: Q=[Qh 16K][Ql 16K]; KV=[Kh 8K][Kl 8K][Vh 8K][Vl 8K], rows 128B, SW128
static __device__ __align__(256) float g_qkv[M_ * QKVN];                   // fp32 qkv (linear)
static __device__ __align__(256) unsigned char g_xs[M_ / 128 * 32 * 16384];        // 16MB  x staged
static __device__ __align__(256) unsigned char g_wqs[QKVN / 128 * 32 * 16384];     // 12MB  Wqkv^T staged
static __device__ __align__(256) unsigned char g_wps[C_ / 128 * 32 * 16384];       // 4MB   Wproj^T staged
static __device__ __align__(256) unsigned char g_os[M_ / 128 * 32 * 16384];        // 16MB  attn out staged
static __device__ __align__(256) unsigned char g_qs[32 * 16 * 32768];              // 16MB  Q blocks
static __device__ __align__(256) unsigned char g_kvs[32 * 32 * 32768];             // 32MB  KV blocks

// ---------------- helpers ----------------
__device__ __forceinline__ uint32_t smem_u32(const void* p) {
    uint32_t a;
    asm("{ .reg .u64 t; cvta.to.shared.u64 t, %1; cvt.u32.u64 %0, t; }" : "=r"(a) : "l"(p));
    return a;
}
__device__ __forceinline__ uint32_t swz(uint32_t o)  { return o ^ ((o >> 3) & 0x70); } // 128B rows
__device__ __forceinline__ uint32_t swz64(uint32_t o){ return o ^ ((o >> 3) & 0x30); } // 64B rows

__device__ __forceinline__ void bulkcp(uint32_t dst, const void* src, uint32_t bytes, uint32_t mbar) {
    asm volatile(
        "cp.async.bulk.shared::cluster.global.mbarrier::complete_tx::bytes [%0], [%1], %2, [%3];"
        :: "r"(dst), "l"(src), "r"(bytes), "r"(mbar) : "memory");
}
#define MBAR_INIT(mbar, cnt) \
    asm volatile("mbarrier.init.shared.b64 [%0], %1;" :: "r"(mbar), "r"((uint32_t)(cnt)) : "memory")
#define MBAR_EXPECT_TX(mbar, tx) \
    asm volatile("mbarrier.arrive.expect_tx.shared.b64 _, [%0], %1;" :: "r"(mbar), "r"((uint32_t)(tx)) : "memory")
__device__ __forceinline__ void mbar_wait(uint32_t mbar, uint32_t parity) {
    uint32_t done;
    asm volatile(
        "{ .reg .pred p; mbarrier.try_wait.parity.acquire.cta.shared::cta.b64 p, [%1], %2; selp.b32 %0, 1, 0, p; }"
        : "=r"(done) : "r"(mbar), "r"(parity) : "memory");
    if (!done) {
        asm volatile(
            "{ .reg .pred P1;\n"
            "WL_%=: mbarrier.try_wait.parity.acquire.cta.shared::cta.b64 P1, [%0], %1, 0x989680;\n"
            "@P1 bra.uni WD_%=; bra.uni WL_%=;\n"
            "WD_%=: }" :: "r"(mbar), "r"(parity) : "memory");
    }
}

__device__ __forceinline__ void ldsm4(uint32_t* r, uint32_t a) {
    asm volatile("ldmatrix.sync.aligned.m8n8.x4.shared.b16 {%0,%1,%2,%3}, [%4];"
                 : "=r"(r[0]), "=r"(r[1]), "=r"(r[2]), "=r"(r[3]) : "r"(a));
}
__device__ __forceinline__ void ldsm4t(uint32_t* r, uint32_t a) {
    asm volatile("ldmatrix.sync.aligned.m8n8.x4.trans.shared.b16 {%0,%1,%2,%3}, [%4];"
                 : "=r"(r[0]), "=r"(r[1]), "=r"(r[2]), "=r"(r[3]) : "r"(a));
}
__device__ __forceinline__ void mma16816(float* c, const uint32_t* a, const uint32_t* b) {
    asm volatile(
        "mma.sync.aligned.m16n8k16.row.col.f32.bf16.bf16.f32 "
        "{%0,%1,%2,%3}, {%4,%5,%6,%7}, {%8,%9}, {%0,%1,%2,%3};"
        : "+f"(c[0]), "+f"(c[1]), "+f"(c[2]), "+f"(c[3])
        : "r"(a[0]), "r"(a[1]), "r"(a[2]), "r"(a[3]), "r"(b[0]), "r"(b[1]));
}
__device__ __forceinline__ uint32_t pack2(float lo, float hi) {
    uint32_t r;
    asm("cvt.rn.bf16x2.f32 %0, %1, %2;" : "=r"(r) : "f"(hi), "f"(lo));
    return r;
}
__device__ __forceinline__ void split2(float a, float b, uint32_t& hi, uint32_t& lo) {
    __nv_bfloat16 xa = __float2bfloat16(a), xb = __float2bfloat16(b);
    hi = pack2(__bfloat162float(xa), __bfloat162float(xb));
    lo = pack2(a - __bfloat162float(xa), b - __bfloat162float(xb));
}

// ---------------------------------------------------------------------------
// cvt_split_staged: fp32 [Mrows,1024] -> staged GEMM-A blocks (hi/lo, SW64).
// thread: 8 consecutive k of one row -> one 16B hi store + one 16B lo store.
// ---------------------------------------------------------------------------
__global__ __launch_bounds__(256) void cvt_split_staged(
    const float* __restrict__ in, unsigned char* __restrict__ out)
{
    int i = blockIdx.x * 256 + threadIdx.x;      // M*128 threads
    int m = i >> 7, k = (i & 127) << 3;
    const float* p = in + (size_t)m * 1024 + k;
    float4 a = ((const float4*)p)[0], b4 = ((const float4*)p)[1];
    uint32_t h[4], l[4];
    split2(a.x, a.y, h[0], l[0]);  split2(a.z, a.w, h[1], l[1]);
    split2(b4.x, b4.y, h[2], l[2]); split2(b4.z, b4.w, h[3], l[3]);
    int rb = m >> 7, row = m & 127, ch = k >> 5, kg = (k & 31) >> 3;
    unsigned char* dst = out + ((size_t)(rb * 32 + ch) << 14);
    uint32_t off = swz64(row * 64 + (kg << 4));
    *(uint4*)(dst + off)        = make_uint4(h[0], h[1], h[2], h[3]);
    *(uint4*)(dst + 8192 + off) = make_uint4(l[0], l[1], l[2], l[3]);
}

// ---------------------------------------------------------------------------
// cvt_transpose_split_staged: W[Kw,Nw] fp32 -> staged GEMM-B (N-major) blocks.
// ---------------------------------------------------------------------------
__global__ __launch_bounds__(128) void cvt_transpose_split_staged(
    const float* __restrict__ W, unsigned char* __restrict__ out, int Nw, int NCH)
{
    __shared__ float t[32][33];
    int tx = threadIdx.x, ty = threadIdx.y;      // (32,4)
    int tid = ty * 32 + tx;
    int n0 = blockIdx.x * 32, k0 = blockIdx.y * 32;
#pragma unroll
    for (int j = 0; j < 8; j++)
        t[ty * 8 + j][tx] = W[(size_t)(k0 + ty * 8 + j) * Nw + n0 + tx];
    __syncthreads();
    int n_local = tid >> 2, kg = tid & 3;
    float v[8];
#pragma unroll
    for (int i = 0; i < 8; i++) v[i] = t[kg * 8 + i][n_local];
    uint32_t h[4], l[4];
#pragma unroll
    for (int i = 0; i < 4; i++) split2(v[2 * i], v[2 * i + 1], h[i], l[i]);
    int nn = n0 + n_local;
    int rb = nn >> 7, row = nn & 127, ch = k0 >> 5;
    unsigned char* dst = out + ((size_t)(rb * NCH + ch) << 14);
    uint32_t off = swz64(row * 64 + (kg << 4));
    *(uint4*)(dst + off)        = make_uint4(h[0], h[1], h[2], h[3]);
    *(uint4*)(dst + 8192 + off) = make_uint4(l[0], l[1], l[2], l[3]);
}

// ---------------------------------------------------------------------------
// HMMA split-bf16 GEMM v4: staged operands, bulk-copy pipeline (3 stages).
// CTA 128x128, 4 warps, warp tile 64x64, BK=32.
// smem: [64B mbar area][stage0 32KB][stage1][stage2]; stage=[Ah][Al][Bh][Bl] 8KB each.
// ---------------------------------------------------------------------------
#define HG_SMEM (1024 + 3 * 32768)

template <bool HAS_BIAS>
__global__ __launch_bounds__(128) void hgemm(
    const unsigned char* __restrict__ As, const unsigned char* __restrict__ Bs,
    const float* __restrict__ bias, float* __restrict__ Cm, int N, int NCH)
{
    extern __shared__ __align__(1024) char smem[];
    const uint32_t sbase = smem_u32(smem);
    const int tid = threadIdx.x;
    const int lane = tid & 31;
    const int wid = tid >> 5;
    const int wm = (wid >> 1) * 64;
    const int wn = (wid & 1) * 64;
    const int brow = blockIdx.y * 128;
    const int bcol = blockIdx.x * 128;

    const unsigned char* Ablk = As + ((size_t)blockIdx.y * NCH << 14);
    const unsigned char* Bblk = Bs + ((size_t)blockIdx.x * NCH << 14);

    if (tid == 0) {
#pragma unroll
        for (int s = 0; s < 3; s++) MBAR_INIT(sbase + s * 8, 1);
    }
    __syncthreads();
    if (tid == 0) {
#pragma unroll
        for (int s = 0; s < 2; s++) {
            uint32_t mb = sbase + s * 8;
            uint32_t st = sbase + 1024 + s * 32768;
            MBAR_EXPECT_TX(mb, 32768);
            bulkcp(st,          Ablk + ((size_t)s << 14), 16384, mb);
            bulkcp(st + 16384,  Bblk + ((size_t)s << 14), 16384, mb);
        }
    }

    float acc[4][8][4];
#pragma unroll
    for (int mt = 0; mt < 4; mt++)
#pragma unroll
        for (int j = 0; j < 8; j++)
#pragma unroll
            for (int i = 0; i < 4; i++) acc[mt][j][i] = 0.f;

    const int T = NCH;
    int cs = 0, cph = 0;   // consumer cursor
    int ps = 2;            // producer slot

    for (int t = 0; t < T; t++) {
        __syncthreads();   // all warps done reading stage t-1 (slot ps)
        if (tid == 0 && t + 2 < T) {
            uint32_t mb = sbase + ps * 8;
            uint32_t st = sbase + 1024 + ps * 32768;
            MBAR_EXPECT_TX(mb, 32768);
            bulkcp(st,         Ablk + ((size_t)(t + 2) << 14), 16384, mb);
            bulkcp(st + 16384, Bblk + ((size_t)(t + 2) << 14), 16384, mb);
        }
        ps = (ps == 2) ? 0 : ps + 1;

        mbar_wait(sbase + cs * 8, cph);
        const uint32_t sAh = sbase + 1024 + cs * 32768;
        const uint32_t sAl = sAh + 8192;
        const uint32_t sBh = sAh + 16384;
        const uint32_t sBl = sAh + 24576;
        if (++cs == 3) { cs = 0; cph ^= 1; }

#pragma unroll
        for (int ks = 0; ks < 2; ks++) {
            uint32_t bfh[8][2], bfl[8][2];
#pragma unroll
            for (int jp = 0; jp < 4; jp++) {
                uint32_t r4[4];
                uint32_t rowb = wn + jp * 16 + (lane & 7) + ((lane >> 4) << 3);
                uint32_t offb = swz64(rowb * 64 + ks * 32 + (((lane >> 3) & 1) << 4));
                ldsm4(r4, sBh + offb);
                bfh[2 * jp][0] = r4[0]; bfh[2 * jp][1] = r4[1];
                bfh[2 * jp + 1][0] = r4[2]; bfh[2 * jp + 1][1] = r4[3];
                ldsm4(r4, sBl + offb);
                bfl[2 * jp][0] = r4[0]; bfl[2 * jp][1] = r4[1];
                bfl[2 * jp + 1][0] = r4[2]; bfl[2 * jp + 1][1] = r4[3];
            }
#pragma unroll
            for (int mp = 0; mp < 2; mp++) {
                uint32_t ah[2][4], al[2][4];
#pragma unroll
                for (int m2 = 0; m2 < 2; m2++) {
                    uint32_t rowa = wm + (mp * 2 + m2) * 16 + (lane & 15);
                    uint32_t offa = swz64(rowa * 64 + ks * 32 + ((lane >> 4) << 4));
                    ldsm4(ah[m2], sAh + offa);
                    ldsm4(al[m2], sAl + offa);
                }
#pragma unroll
                for (int m2 = 0; m2 < 2; m2++)
#pragma unroll
                    for (int j = 0; j < 8; j++)
                        mma16816(acc[mp * 2 + m2][j], ah[m2], bfh[j]);
#pragma unroll
                for (int m2 = 0; m2 < 2; m2++)
#pragma unroll
                    for (int j = 0; j < 8; j++)
                        mma16816(acc[mp * 2 + m2][j], ah[m2], bfl[j]);
#pragma unroll
                for (int m2 = 0; m2 < 2; m2++)
#pragma unroll
                    for (int j = 0; j < 8; j++)
                        mma16816(acc[mp * 2 + m2][j], al[m2], bfh[j]);
            }
        }
    }

    // epilogue
#pragma unroll
    for (int mt = 0; mt < 4; mt++) {
        int r0 = brow + wm + mt * 16 + (lane >> 2);
#pragma unroll
        for (int j = 0; j < 8; j++) {
            int col = bcol + wn + j * 8 + (lane & 3) * 2;
            float bx = 0.f, by = 0.f;
            if (HAS_BIAS) { bx = bias[col]; by = bias[col + 1]; }
            *(float2*)(Cm + (size_t)r0 * N + col) =
                make_float2(acc[mt][j][0] + bx, acc[mt][j][1] + by);
            *(float2*)(Cm + (size_t)(r0 + 8) * N + col) =
                make_float2(acc[mt][j][2] + bx, acc[mt][j][3] + by);
        }
    }
}

// ---------------------------------------------------------------------------
// ln_split_staged: LN q,k + plain v from g_qkv; write staged Q / packed-KV blocks.
// One warp per 64-elem head row; lane owns elems (2*lane, 2*lane+1).
// ---------------------------------------------------------------------------
__global__ __launch_bounds__(256) void ln_split(
    const float* __restrict__ qkv,
    const float* __restrict__ qw, const float* __restrict__ qb,
    const float* __restrict__ kw, const float* __restrict__ kb,
    unsigned char* __restrict__ qs, unsigned char* __restrict__ kvs)
{
    int gwarp = (blockIdx.x * blockDim.x + threadIdx.x) >> 5;
    int lane = threadIdx.x & 31;
    const int ROWS = M_ * H_;
    int mtx = (gwarp >= 2 * ROWS) ? 2 : (gwarp >= ROWS ? 1 : 0);
    int r = gwarp - mtx * ROWS;
    int bn = r >> 4;
    int h = r & 15;
    const float* src = qkv + (size_t)bn * QKVN + mtx * C_ + h * HD_;

    float2 xv = *(const float2*)(src + 2 * lane);
    float x0 = xv.x, x1 = xv.y;

    if (mtx < 2) {
        float s = x0 + x1;
#pragma unroll
        for (int o = 16; o > 0; o >>= 1) s += __shfl_xor_sync(0xffffffffu, s, o);
        float mu = s * (1.0f / 64.0f);
        float d0 = x0 - mu, d1 = x1 - mu;
        float v = d0 * d0 + d1 * d1;
#pragma unroll
        for (int o = 16; o > 0; o >>= 1) v += __shfl_xor_sync(0xffffffffu, v, o);
        float rinv = rsqrtf(v * (1.0f / 64.0f) + 1e-5f);
        const float* w = mtx == 0 ? qw : kw;
        const float* bb = mtx == 0 ? qb : kb;
        float2 wv = *(const float2*)(w + 2 * lane);
        float2 bv = *(const float2*)(bb + 2 * lane);
        float sc = mtx == 0 ? (0.125f * LOG2E) : 1.0f;
        x0 = (d0 * rinv * wv.x + bv.x) * sc;
        x1 = (d1 * rinv * wv.y + bv.y) * sc;
    }

    int b = bn >> 11;
    int n = bn & (N_ - 1);
    int bh = b * H_ + h;
    uint32_t hi, lo;
    split2(x0, x1, hi, lo);

    if (mtx == 0) {
        int qblk = n >> 7, row = n & 127;
        unsigned char* base = qs + ((size_t)(bh * 16 + qblk) << 15);
        uint32_t off = swz(row * 128 + lane * 4);
        *(uint32_t*)(base + off)         = hi;
        *(uint32_t*)(base + 16384 + off) = lo;
    } else {
        int ch = n >> 6, row = n & 63;
        unsigned char* base = kvs + ((size_t)(bh * 32 + ch) << 15) + (mtx == 2 ? 16384 : 0);
        uint32_t off = swz(row * 128 + lane * 4);
        *(uint32_t*)(base + off)        = hi;
        *(uint32_t*)(base + 8192 + off) = lo;
    }
}

// ---------------------------------------------------------------------------
// HMMA flash attention v4: staged Q/KV, bulk-copy 2-stage pipeline.
// smem: [64B mbars][Q 32KB][stage0 32KB][stage1 32KB]
// ---------------------------------------------------------------------------
#define AT_SMEM (1024 + 32768 + 2 * 32768)

__global__ __launch_bounds__(128) void attn_hmma(
    const unsigned char* __restrict__ qs, const unsigned char* __restrict__ kvs,
    unsigned char* __restrict__ os)
{
    extern __shared__ __align__(1024) char smem[];
    const uint32_t sbase = smem_u32(smem);
    const int tid = threadIdx.x;
    const int lane = tid & 31;
    const int w = tid >> 5;
    const int bh = blockIdx.y;
    const int q0 = blockIdx.x * 128;

    const uint32_t mq = sbase;
    const uint32_t sQ = sbase + 1024;
    const unsigned char* kvblk = kvs + ((size_t)bh << 20);   // bh * 32 * 32768

    if (tid == 0) {
        MBAR_INIT(mq, 1);
        MBAR_INIT(sbase + 8, 1);
        MBAR_INIT(sbase + 16, 1);
    }
    __syncthreads();
    if (tid == 0) {
        MBAR_EXPECT_TX(mq, 32768);
        bulkcp(sQ, qs + ((size_t)(bh * 16 + blockIdx.x) << 15), 32768, mq);
        MBAR_EXPECT_TX(sbase + 8, 32768);
        bulkcp(sQ + 32768, kvblk, 32768, sbase + 8);
    }

    float oac[2][8][4];
#pragma unroll
    for (int mt = 0; mt < 2; mt++)
#pragma unroll
        for (int j = 0; j < 8; j++)
#pragma unroll
            for (int i = 0; i < 4; i++) oac[mt][j][i] = 0.f;
    float mm[2][2], ll[2][2];
#pragma unroll
    for (int mt = 0; mt < 2; mt++) {
        mm[mt][0] = -INFINITY; mm[mt][1] = -INFINITY;
        ll[mt][0] = 0.f; ll[mt][1] = 0.f;
    }

    const int T = N_ / 64;     // 32
    for (int t = 0; t < T; t++) {
        __syncthreads();       // all warps done reading stage t-1
        if (tid == 0 && t + 1 < T) {
            int s = (t + 1) & 1;
            uint32_t mb = sbase + 8 + s * 8;
            MBAR_EXPECT_TX(mb, 32768);
            bulkcp(sQ + 32768 + s * 32768, kvblk + ((size_t)(t + 1) << 15), 32768, mb);
        }
        if (t == 0) mbar_wait(mq, 0);
        mbar_wait(sbase + 8 + (t & 1) * 8, (t >> 1) & 1);

        const uint32_t sK = sQ + 32768 + (t & 1) * 32768;
        const uint32_t sV = sK + 16384;

        // ---- S = Q @ K^T ----
        float s[2][8][4];
#pragma unroll
        for (int mt = 0; mt < 2; mt++)
#pragma unroll
            for (int j = 0; j < 8; j++)
#pragma unroll
                for (int i = 0; i < 4; i++) s[mt][j][i] = 0.f;

#pragma unroll
        for (int kt = 0; kt < 4; kt++) {
            uint32_t kfh[8][2], kfl[8][2];
#pragma unroll
            for (int jp = 0; jp < 4; jp++) {
                uint32_t r4[4];
                uint32_t rowb = jp * 16 + (lane & 7) + ((lane >> 4) << 3);
                uint32_t off = swz(rowb * 128 + kt * 32 + (((lane >> 3) & 1) << 4));
                ldsm4(r4, sK + off);
                kfh[2 * jp][0] = r4[0]; kfh[2 * jp][1] = r4[1];
                kfh[2 * jp + 1][0] = r4[2]; kfh[2 * jp + 1][1] = r4[3];
                ldsm4(r4, sK + 8192 + off);
                kfl[2 * jp][0] = r4[0]; kfl[2 * jp][1] = r4[1];
                kfl[2 * jp + 1][0] = r4[2]; kfl[2 * jp + 1][1] = r4[3];
            }
            uint32_t qf[2][4], qg[2][4];
#pragma unroll
            for (int mt = 0; mt < 2; mt++) {
                uint32_t rowa = w * 32 + mt * 16 + (lane & 15);
                uint32_t off = swz(rowa * 128 + kt * 32 + ((lane >> 4) << 4));
                ldsm4(qf[mt], sQ + off);
                ldsm4(qg[mt], sQ + 16384 + off);
            }
#pragma unroll
            for (int mt = 0; mt < 2; mt++)
#pragma unroll
                for (int j = 0; j < 8; j++)
                    mma16816(s[mt][j], qf[mt], kfh[j]);
#pragma unroll
            for (int mt = 0; mt < 2; mt++)
#pragma unroll
                for (int j = 0; j < 8; j++)
                    mma16816(s[mt][j], qf[mt], kfl[j]);
#pragma unroll
            for (int mt = 0; mt < 2; mt++)
#pragma unroll
                for (int j = 0; j < 8; j++)
                    mma16816(s[mt][j], qg[mt], kfh[j]);
        }

        // ---- online softmax ----
#pragma unroll
        for (int mt = 0; mt < 2; mt++) {
            float mx0 = -INFINITY, mx1 = -INFINITY;
#pragma unroll
            for (int j = 0; j < 8; j++) {
                mx0 = fmaxf(mx0, fmaxf(s[mt][j][0], s[mt][j][1]));
                mx1 = fmaxf(mx1, fmaxf(s[mt][j][2], s[mt][j][3]));
            }
            mx0 = fmaxf(mx0, __shfl_xor_sync(0xffffffffu, mx0, 1));
            mx0 = fmaxf(mx0, __shfl_xor_sync(0xffffffffu, mx0, 2));
            mx1 = fmaxf(mx1, __shfl_xor_sync(0xffffffffu, mx1, 1));
            mx1 = fmaxf(mx1, __shfl_xor_sync(0xffffffffu, mx1, 2));
            float mn0 = fmaxf(mm[mt][0], mx0), mn1 = fmaxf(mm[mt][1], mx1);
            float c0 = exp2f(mm[mt][0] - mn0), c1 = exp2f(mm[mt][1] - mn1);
            mm[mt][0] = mn0; mm[mt][1] = mn1;
            float rs0 = 0.f, rs1 = 0.f;
#pragma unroll
            for (int j = 0; j < 8; j++) {
                s[mt][j][0] = exp2f(s[mt][j][0] - mn0);
                s[mt][j][1] = exp2f(s[mt][j][1] - mn0);
                s[mt][j][2] = exp2f(s[mt][j][2] - mn1);
                s[mt][j][3] = exp2f(s[mt][j][3] - mn1);
                rs0 += s[mt][j][0] + s[mt][j][1];
                rs1 += s[mt][j][2] + s[mt][j][3];
            }
            rs0 += __shfl_xor_sync(0xffffffffu, rs0, 1);
            rs0 += __shfl_xor_sync(0xffffffffu, rs0, 2);
            rs1 += __shfl_xor_sync(0xffffffffu, rs1, 1);
            rs1 += __shfl_xor_sync(0xffffffffu, rs1, 2);
            ll[mt][0] = ll[mt][0] * c0 + rs0;
            ll[mt][1] = ll[mt][1] * c1 + rs1;
#pragma unroll
            for (int j = 0; j < 8; j++) {
                oac[mt][j][0] *= c0; oac[mt][j][1] *= c0;
                oac[mt][j][2] *= c1; oac[mt][j][3] *= c1;
            }
        }

        // ---- O += P @ V ----
#pragma unroll
        for (int kt2 = 0; kt2 < 4; kt2++) {
            uint32_t vfh[8][2], vfl[8][2];
#pragma unroll
            for (int hjp = 0; hjp < 4; hjp++) {
                uint32_t r4[4];
                uint32_t off = swz((kt2 * 16 + (lane & 15)) * 128 +
                                   hjp * 32 + ((lane >> 4) << 4));
                ldsm4t(r4, sV + off);
                vfh[2 * hjp][0] = r4[0]; vfh[2 * hjp][1] = r4[1];
                vfh[2 * hjp + 1][0] = r4[2]; vfh[2 * hjp + 1][1] = r4[3];
                ldsm4t(r4, sV + 8192 + off);
                vfl[2 * hjp][0] = r4[0]; vfl[2 * hjp][1] = r4[1];
                vfl[2 * hjp + 1][0] = r4[2]; vfl[2 * hjp + 1][1] = r4[3];
            }
            uint32_t pfh[2][4], pfl[2][4];
#pragma unroll
            for (int mt = 0; mt < 2; mt++) {
                split2(s[mt][2 * kt2][0],     s[mt][2 * kt2][1],     pfh[mt][0], pfl[mt][0]);
                split2(s[mt][2 * kt2][2],     s[mt][2 * kt2][3],     pfh[mt][1], pfl[mt][1]);
                split2(s[mt][2 * kt2 + 1][0], s[mt][2 * kt2 + 1][1], pfh[mt][2], pfl[mt][2]);
                split2(s[mt][2 * kt2 + 1][2], s[mt][2 * kt2 + 1][3], pfh[mt][3], pfl[mt][3]);
            }
#pragma unroll
            for (int mt = 0; mt < 2; mt++)
#pragma unroll
                for (int hj = 0; hj < 8; hj++)
                    mma16816(oac[mt][hj], pfh[mt], vfh[hj]);
#pragma unroll
            for (int mt = 0; mt < 2; mt++)
#pragma unroll
                for (int hj = 0; hj < 8; hj++)
                    mma16816(oac[mt][hj], pfh[mt], vfl[hj]);
#pragma unroll
            for (int mt = 0; mt < 2; mt++)
#pragma unroll
                for (int hj = 0; hj < 8; hj++)
                    mma16816(oac[mt][hj], pfl[mt], vfh[hj]);
        }
    }

    // ---- epilogue: normalize, split, write staged GEMM-A blocks ----
    int b = bh >> 4, h = bh & 15;
#pragma unroll
    for (int mt = 0; mt < 2; mt++) {
        float il0 = 1.0f / ll[mt][0], il1 = 1.0f / ll[mt][1];
        int r0 = b * N_ + q0 + w * 32 + mt * 16 + (lane >> 2);
#pragma unroll
        for (int hj = 0; hj < 8; hj++) {
            int c = h * 64 + hj * 8 + (lane & 3) * 2;
            int ch = c >> 5;
            uint32_t koff = (c & 31) * 2;
#pragma unroll
            for (int half = 0; half < 2; half++) {
                int rr = r0 + half * 8;
                int rb = rr >> 7, rowm = rr & 127;
                unsigned char* bo = os + ((size_t)(rb * 32 + ch) << 14);
                uint32_t off = swz64(rowm * 64 + koff);
                uint32_t hi, lo;
                if (half == 0) split2(oac[mt][hj][0] * il0, oac[mt][hj][1] * il0, hi, lo);
                else           split2(oac[mt][hj][2] * il1, oac[mt][hj][3] * il1, hi, lo);
                *(uint32_t*)(bo + off)        = hi;
                *(uint32_t*)(bo + 8192 + off) = lo;
            }
        }
    }
}

// ---------------------------------------------------------------------------
// Launch
// ---------------------------------------------------------------------------
extern "C" void kernel_launch(void* const* d_in, const int* in_sizes, int n_in,
                              void* d_out, int out_size)
{
    const float* x     = (const float*)d_in[0];
    const float* Wqkv  = (const float*)d_in[1];
    const float* qnw   = (const float*)d_in[2];
    const float* qnb   = (const float*)d_in[3];
    const float* knw   = (const float*)d_in[4];
    const float* knb   = (const float*)d_in[5];
    const float* Wproj = (const float*)d_in[6];
    const float* bproj = (const float*)d_in[7];
    float* out = (float*)d_out;

    float* qkv;
    unsigned char *xs, *wqs, *wps, *os, *qsp, *kvs;
    cudaGetSymbolAddress((void**)&qkv, g_qkv);
    cudaGetSymbolAddress((void**)&xs, g_xs);
    cudaGetSymbolAddress((void**)&wqs, g_wqs);
    cudaGetSymbolAddress((void**)&wps, g_wps);
    cudaGetSymbolAddress((void**)&os, g_os);
    cudaGetSymbolAddress((void**)&qsp, g_qs);
    cudaGetSymbolAddress((void**)&kvs, g_kvs);

    cudaFuncSetAttribute(hgemm<false>, cudaFuncAttributeMaxDynamicSharedMemorySize, HG_SMEM);
    cudaFuncSetAttribute(hgemm<true>, cudaFuncAttributeMaxDynamicSharedMemorySize, HG_SMEM);
    cudaFuncSetAttribute(attn_hmma, cudaFuncAttributeMaxDynamicSharedMemorySize, AT_SMEM);

    // 0) stage inputs & weights
    cvt_split_staged<<<M_ * 128 / 256, 256>>>(x, xs);
    cvt_transpose_split_staged<<<dim3(QKVN / 32, C_ / 32), dim3(32, 4)>>>(Wqkv, wqs, QKVN, 32);
    cvt_transpose_split_staged<<<dim3(C_ / 32, C_ / 32), dim3(32, 4)>>>(Wproj, wps, C_, 32);

    // 1) QKV GEMM
    hgemm<false><<<dim3(QKVN / 128, M_ / 128), 128, HG_SMEM>>>(xs, wqs, nullptr, qkv, QKVN, 32);

    // 2) LN + stage q/k/v
    ln_split<<<3 * M_ * H_ / 8, 256>>>(qkv, qnw, qnb, knw, knb, qsp, kvs);

    // 3) flash attention -> staged proj-A
    attn_hmma<<<dim3(N_ / 128, B_ * H_), 128, AT_SMEM>>>(qsp, kvs, os);

    // 4) proj GEMM + bias
    hgemm<true><<<dim3(C_ / 128, M_ / 128), 128, HG_SMEM>>>(os, wps, bproj, out, C_, 32);
}

// round 13
// speedup vs baseline: 1.0005x; 1.0005x over previous
#include <cuda_runtime.h>
#include <cuda_bf16.h>
#include <math.h>
#include <stdint.h>

#define B_  2
#define N_  2048
#define C_  1024
#define H_  16
#define HD_ 64
#define M_  (B_ * N_)      // 4096
#define QKVN (3 * C_)      // 3072
#define LOG2E 1.4426950408889634f

// ---------------- scratch ----------------
// staged layouts: 16KB GEMM blocks = [hi 8K][lo 8K], rows of 64B, SW64 swizzle
//                 32KB attn blocks: Q=[Qh 16K][Ql 16K]; KV=[Kh 8K][Kl 8K][Vh 8K][Vl 8K], rows 128B, SW128
static __device__ __align__(256) float g_qkv[M_ * QKVN];                   // fp32 qkv (linear)
static __device__ __align__(256) unsigned char g_xs[M_ / 128 * 32 * 16384];        // 16MB  x staged
static __device__ __align__(256) unsigned char g_wqs[QKVN / 128 * 32 * 16384];     // 12MB  Wqkv^T staged
static __device__ __align__(256) unsigned char g_wps[C_ / 128 * 32 * 16384];       // 4MB   Wproj^T staged
static __device__ __align__(256) unsigned char g_os[M_ / 128 * 32 * 16384];        // 16MB  attn out staged
static __device__ __align__(256) unsigned char g_qs[32 * 16 * 32768];              // 16MB  Q blocks
static __device__ __align__(256) unsigned char g_kvs[32 * 32 * 32768];             // 32MB  KV blocks

// ---------------- helpers ----------------
__device__ __forceinline__ uint32_t smem_u32(const void* p) {
    uint32_t a;
    asm("{ .reg .u64 t; cvta.to.shared.u64 t, %1; cvt.u32.u64 %0, t; }" : "=r"(a) : "l"(p));
    return a;
}
__device__ __forceinline__ uint32_t swz(uint32_t o)  { return o ^ ((o >> 3) & 0x70); } // 128B rows
__device__ __forceinline__ uint32_t swz64(uint32_t o){ return o ^ ((o >> 3) & 0x30); } // 64B rows

__device__ __forceinline__ void bulkcp(uint32_t dst, const void* src, uint32_t bytes, uint32_t mbar) {
    asm volatile(
        "cp.async.bulk.shared::cluster.global.mbarrier::complete_tx::bytes [%0], [%1], %2, [%3];"
        :: "r"(dst), "l"(src), "r"(bytes), "r"(mbar) : "memory");
}
#define MBAR_INIT(mbar, cnt) \
    asm volatile("mbarrier.init.shared.b64 [%0], %1;" :: "r"(mbar), "r"((uint32_t)(cnt)) : "memory")
#define MBAR_EXPECT_TX(mbar, tx) \
    asm volatile("mbarrier.arrive.expect_tx.shared.b64 _, [%0], %1;" :: "r"(mbar), "r"((uint32_t)(tx)) : "memory")
__device__ __forceinline__ void mbar_wait(uint32_t mbar, uint32_t parity) {
    uint32_t done;
    asm volatile(
        "{ .reg .pred p; mbarrier.try_wait.parity.acquire.cta.shared::cta.b64 p, [%1], %2; selp.b32 %0, 1, 0, p; }"
        : "=r"(done) : "r"(mbar), "r"(parity) : "memory");
    if (!done) {
        asm volatile(
            "{ .reg .pred P1;\n"
            "WL_%=: mbarrier.try_wait.parity.acquire.cta.shared::cta.b64 P1, [%0], %1, 0x989680;\n"
            "@P1 bra.uni WD_%=; bra.uni WL_%=;\n"
            "WD_%=: }" :: "r"(mbar), "r"(parity) : "memory");
    }
}

__device__ __forceinline__ void ldsm4(uint32_t* r, uint32_t a) {
    asm volatile("ldmatrix.sync.aligned.m8n8.x4.shared.b16 {%0,%1,%2,%3}, [%4];"
                 : "=r"(r[0]), "=r"(r[1]), "=r"(r[2]), "=r"(r[3]) : "r"(a));
}
__device__ __forceinline__ void ldsm4t(uint32_t* r, uint32_t a) {
    asm volatile("ldmatrix.sync.aligned.m8n8.x4.trans.shared.b16 {%0,%1,%2,%3}, [%4];"
                 : "=r"(r[0]), "=r"(r[1]), "=r"(r[2]), "=r"(r[3]) : "r"(a));
}
__device__ __forceinline__ void mma16816(float* c, const uint32_t* a, const uint32_t* b) {
    asm volatile(
        "mma.sync.aligned.m16n8k16.row.col.f32.bf16.bf16.f32 "
        "{%0,%1,%2,%3}, {%4,%5,%6,%7}, {%8,%9}, {%0,%1,%2,%3};"
        : "+f"(c[0]), "+f"(c[1]), "+f"(c[2]), "+f"(c[3])
        : "r"(a[0]), "r"(a[1]), "r"(a[2]), "r"(a[3]), "r"(b[0]), "r"(b[1]));
}
__device__ __forceinline__ uint32_t pack2(float lo, float hi) {
    uint32_t r;
    asm("cvt.rn.bf16x2.f32 %0, %1, %2;" : "=r"(r) : "f"(hi), "f"(lo));
    return r;
}
__device__ __forceinline__ void split2(float a, float b, uint32_t& hi, uint32_t& lo) {
    __nv_bfloat16 xa = __float2bfloat16(a), xb = __float2bfloat16(b);
    hi = pack2(__bfloat162float(xa), __bfloat162float(xb));
    lo = pack2(a - __bfloat162float(xa), b - __bfloat162float(xb));
}

// ---------------------------------------------------------------------------
// cvt_split_staged: fp32 [Mrows,1024] -> staged GEMM-A blocks (hi/lo, SW64).
// thread: 8 consecutive k of one row -> one 16B hi store + one 16B lo store.
// ---------------------------------------------------------------------------
__global__ __launch_bounds__(256) void cvt_split_staged(
    const float* __restrict__ in, unsigned char* __restrict__ out)
{
    int i = blockIdx.x * 256 + threadIdx.x;      // M*128 threads
    int m = i >> 7, k = (i & 127) << 3;
    const float* p = in + (size_t)m * 1024 + k;
    float4 a = ((const float4*)p)[0], b4 = ((const float4*)p)[1];
    uint32_t h[4], l[4];
    split2(a.x, a.y, h[0], l[0]);  split2(a.z, a.w, h[1], l[1]);
    split2(b4.x, b4.y, h[2], l[2]); split2(b4.z, b4.w, h[3], l[3]);
    int rb = m >> 7, row = m & 127, ch = k >> 5, kg = (k & 31) >> 3;
    unsigned char* dst = out + ((size_t)(rb * 32 + ch) << 14);
    uint32_t off = swz64(row * 64 + (kg << 4));
    *(uint4*)(dst + off)        = make_uint4(h[0], h[1], h[2], h[3]);
    *(uint4*)(dst + 8192 + off) = make_uint4(l[0], l[1], l[2], l[3]);
}

// ---------------------------------------------------------------------------
// cvt_transpose_split_staged: W[Kw,Nw] fp32 -> staged GEMM-B (N-major) blocks.
// ---------------------------------------------------------------------------
__global__ __launch_bounds__(128) void cvt_transpose_split_staged(
    const float* __restrict__ W, unsigned char* __restrict__ out, int Nw, int NCH)
{
    __shared__ float t[32][33];
    int tx = threadIdx.x, ty = threadIdx.y;      // (32,4)
    int tid = ty * 32 + tx;
    int n0 = blockIdx.x * 32, k0 = blockIdx.y * 32;
#pragma unroll
    for (int j = 0; j < 8; j++)
        t[ty * 8 + j][tx] = W[(size_t)(k0 + ty * 8 + j) * Nw + n0 + tx];
    __syncthreads();
    int n_local = tid >> 2, kg = tid & 3;
    float v[8];
#pragma unroll
    for (int i = 0; i < 8; i++) v[i] = t[kg * 8 + i][n_local];
    uint32_t h[4], l[4];
#pragma unroll
    for (int i = 0; i < 4; i++) split2(v[2 * i], v[2 * i + 1], h[i], l[i]);
    int nn = n0 + n_local;
    int rb = nn >> 7, row = nn & 127, ch = k0 >> 5;
    unsigned char* dst = out + ((size_t)(rb * NCH + ch) << 14);
    uint32_t off = swz64(row * 64 + (kg << 4));
    *(uint4*)(dst + off)        = make_uint4(h[0], h[1], h[2], h[3]);
    *(uint4*)(dst + 8192 + off) = make_uint4(l[0], l[1], l[2], l[3]);
}

// ---------------------------------------------------------------------------
// HMMA split-bf16 GEMM v4: staged operands, bulk-copy pipeline (3 stages).
// CTA 128x128, 4 warps, warp tile 64x64, BK=32.
// smem: [64B mbar area][stage0 32KB][stage1][stage2]; stage=[Ah][Al][Bh][Bl] 8KB each.
// ---------------------------------------------------------------------------
#define HG_SMEM (1024 + 3 * 32768)

template <bool HAS_BIAS>
__global__ __launch_bounds__(128) void hgemm(
    const unsigned char* __restrict__ As, const unsigned char* __restrict__ Bs,
    const float* __restrict__ bias, float* __restrict__ Cm, int N, int NCH)
{
    extern __shared__ __align__(1024) char smem[];
    const uint32_t sbase = smem_u32(smem);
    const int tid = threadIdx.x;
    const int lane = tid & 31;
    const int wid = tid >> 5;
    const int wm = (wid >> 1) * 64;
    const int wn = (wid & 1) * 64;
    const int brow = blockIdx.y * 128;
    const int bcol = blockIdx.x * 128;

    const unsigned char* Ablk = As + ((size_t)blockIdx.y * NCH << 14);
    const unsigned char* Bblk = Bs + ((size_t)blockIdx.x * NCH << 14);

    if (tid == 0) {
#pragma unroll
        for (int s = 0; s < 3; s++) MBAR_INIT(sbase + s * 8, 1);
    }
    __syncthreads();
    if (tid == 0) {
#pragma unroll
        for (int s = 0; s < 2; s++) {
            uint32_t mb = sbase + s * 8;
            uint32_t st = sbase + 1024 + s * 32768;
            MBAR_EXPECT_TX(mb, 32768);
            bulkcp(st,          Ablk + ((size_t)s << 14), 16384, mb);
            bulkcp(st + 16384,  Bblk + ((size_t)s << 14), 16384, mb);
        }
    }

    float acc[4][8][4];
#pragma unroll
    for (int mt = 0; mt < 4; mt++)
#pragma unroll
        for (int j = 0; j < 8; j++)
#pragma unroll
            for (int i = 0; i < 4; i++) acc[mt][j][i] = 0.f;

    const int T = NCH;
    int cs = 0, cph = 0;   // consumer cursor
    int ps = 2;            // producer slot

    for (int t = 0; t < T; t++) {
        __syncthreads();   // all warps done reading stage t-1 (slot ps)
        if (tid == 0 && t + 2 < T) {
            uint32_t mb = sbase + ps * 8;
            uint32_t st = sbase + 1024 + ps * 32768;
            MBAR_EXPECT_TX(mb, 32768);
            bulkcp(st,         Ablk + ((size_t)(t + 2) << 14), 16384, mb);
            bulkcp(st + 16384, Bblk + ((size_t)(t + 2) << 14), 16384, mb);
        }
        ps = (ps == 2) ? 0 : ps + 1;

        mbar_wait(sbase + cs * 8, cph);
        const uint32_t sAh = sbase + 1024 + cs * 32768;
        const uint32_t sAl = sAh + 8192;
        const uint32_t sBh = sAh + 16384;
        const uint32_t sBl = sAh + 24576;
        if (++cs == 3) { cs = 0; cph ^= 1; }

#pragma unroll
        for (int ks = 0; ks < 2; ks++) {
            uint32_t bfh[8][2], bfl[8][2];
#pragma unroll
            for (int jp = 0; jp < 4; jp++) {
                uint32_t r4[4];
                uint32_t rowb = wn + jp * 16 + (lane & 7) + ((lane >> 4) << 3);
                uint32_t offb = swz64(rowb * 64 + ks * 32 + (((lane >> 3) & 1) << 4));
                ldsm4(r4, sBh + offb);
                bfh[2 * jp][0] = r4[0]; bfh[2 * jp][1] = r4[1];
                bfh[2 * jp + 1][0] = r4[2]; bfh[2 * jp + 1][1] = r4[3];
                ldsm4(r4, sBl + offb);
                bfl[2 * jp][0] = r4[0]; bfl[2 * jp][1] = r4[1];
                bfl[2 * jp + 1][0] = r4[2]; bfl[2 * jp + 1][1] = r4[3];
            }
#pragma unroll
            for (int mp = 0; mp < 2; mp++) {
                uint32_t ah[2][4], al[2][4];
#pragma unroll
                for (int m2 = 0; m2 < 2; m2++) {
                    uint32_t rowa = wm + (mp * 2 + m2) * 16 + (lane & 15);
                    uint32_t offa = swz64(rowa * 64 + ks * 32 + ((lane >> 4) << 4));
                    ldsm4(ah[m2], sAh + offa);
                    ldsm4(al[m2], sAl + offa);
                }
#pragma unroll
                for (int m2 = 0; m2 < 2; m2++)
#pragma unroll
                    for (int j = 0; j < 8; j++)
                        mma16816(acc[mp * 2 + m2][j], ah[m2], bfh[j]);
#pragma unroll
                for (int m2 = 0; m2 < 2; m2++)
#pragma unroll
                    for (int j = 0; j < 8; j++)
                        mma16816(acc[mp * 2 + m2][j], ah[m2], bfl[j]);
#pragma unroll
                for (int m2 = 0; m2 < 2; m2++)
#pragma unroll
                    for (int j = 0; j < 8; j++)
                        mma16816(acc[mp * 2 + m2][j], al[m2], bfh[j]);
            }
        }
    }

    // epilogue
#pragma unroll
    for (int mt = 0; mt < 4; mt++) {
        int r0 = brow + wm + mt * 16 + (lane >> 2);
#pragma unroll
        for (int j = 0; j < 8; j++) {
            int col = bcol + wn + j * 8 + (lane & 3) * 2;
            float bx = 0.f, by = 0.f;
            if (HAS_BIAS) { bx = bias[col]; by = bias[col + 1]; }
            *(float2*)(Cm + (size_t)r0 * N + col) =
                make_float2(acc[mt][j][0] + bx, acc[mt][j][1] + by);
            *(float2*)(Cm + (size_t)(r0 + 8) * N + col) =
                make_float2(acc[mt][j][2] + bx, acc[mt][j][3] + by);
        }
    }
}

// ---------------------------------------------------------------------------
// ln_split_staged: LN q,k + plain v from g_qkv; write staged Q / packed-KV blocks.
// One warp per 64-elem head row; lane owns elems (2*lane, 2*lane+1).
// ---------------------------------------------------------------------------
__global__ __launch_bounds__(256) void ln_split(
    const float* __restrict__ qkv,
    const float* __restrict__ qw, const float* __restrict__ qb,
    const float* __restrict__ kw, const float* __restrict__ kb,
    unsigned char* __restrict__ qs, unsigned char* __restrict__ kvs)
{
    int gwarp = (blockIdx.x * blockDim.x + threadIdx.x) >> 5;
    int lane = threadIdx.x & 31;
    const int ROWS = M_ * H_;
    int mtx = (gwarp >= 2 * ROWS) ? 2 : (gwarp >= ROWS ? 1 : 0);
    int r = gwarp - mtx * ROWS;
    int bn = r >> 4;
    int h = r & 15;
    const float* src = qkv + (size_t)bn * QKVN + mtx * C_ + h * HD_;

    float2 xv = *(const float2*)(src + 2 * lane);
    float x0 = xv.x, x1 = xv.y;

    if (mtx < 2) {
        float s = x0 + x1;
#pragma unroll
        for (int o = 16; o > 0; o >>= 1) s += __shfl_xor_sync(0xffffffffu, s, o);
        float mu = s * (1.0f / 64.0f);
        float d0 = x0 - mu, d1 = x1 - mu;
        float v = d0 * d0 + d1 * d1;
#pragma unroll
        for (int o = 16; o > 0; o >>= 1) v += __shfl_xor_sync(0xffffffffu, v, o);
        float rinv = rsqrtf(v * (1.0f / 64.0f) + 1e-5f);
        const float* w = mtx == 0 ? qw : kw;
        const float* bb = mtx == 0 ? qb : kb;
        float2 wv = *(const float2*)(w + 2 * lane);
        float2 bv = *(const float2*)(bb + 2 * lane);
        float sc = mtx == 0 ? (0.125f * LOG2E) : 1.0f;
        x0 = (d0 * rinv * wv.x + bv.x) * sc;
        x1 = (d1 * rinv * wv.y + bv.y) * sc;
    }

    int b = bn >> 11;
    int n = bn & (N_ - 1);
    int bh = b * H_ + h;
    uint32_t hi, lo;
    split2(x0, x1, hi, lo);

    if (mtx == 0) {
        int qblk = n >> 7, row = n & 127;
        unsigned char* base = qs + ((size_t)(bh * 16 + qblk) << 15);
        uint32_t off = swz(row * 128 + lane * 4);
        *(uint32_t*)(base + off)         = hi;
        *(uint32_t*)(base + 16384 + off) = lo;
    } else {
        int ch = n >> 6, row = n & 63;
        unsigned char* base = kvs + ((size_t)(bh * 32 + ch) << 15) + (mtx == 2 ? 16384 : 0);
        uint32_t off = swz(row * 128 + lane * 4);
        *(uint32_t*)(base + off)        = hi;
        *(uint32_t*)(base + 8192 + off) = lo;
    }
}

// ---------------------------------------------------------------------------
// HMMA flash attention v4: staged Q/KV, bulk-copy 2-stage pipeline.
// smem: [64B mbars][Q 32KB][stage0 32KB][stage1 32KB]
// ---------------------------------------------------------------------------
#define AT_SMEM (1024 + 32768 + 2 * 32768)

__global__ __launch_bounds__(128) void attn_hmma(
    const unsigned char* __restrict__ qs, const unsigned char* __restrict__ kvs,
    unsigned char* __restrict__ os)
{
    extern __shared__ __align__(1024) char smem[];
    const uint32_t sbase = smem_u32(smem);
    const int tid = threadIdx.x;
    const int lane = tid & 31;
    const int w = tid >> 5;
    const int bh = blockIdx.y;
    const int q0 = blockIdx.x * 128;

    const uint32_t mq = sbase;
    const uint32_t sQ = sbase + 1024;
    const unsigned char* kvblk = kvs + ((size_t)bh << 20);   // bh * 32 * 32768

    if (tid == 0) {
        MBAR_INIT(mq, 1);
        MBAR_INIT(sbase + 8, 1);
        MBAR_INIT(sbase + 16, 1);
    }
    __syncthreads();
    if (tid == 0) {
        MBAR_EXPECT_TX(mq, 32768);
        bulkcp(sQ, qs + ((size_t)(bh * 16 + blockIdx.x) << 15), 32768, mq);
        MBAR_EXPECT_TX(sbase + 8, 32768);
        bulkcp(sQ + 32768, kvblk, 32768, sbase + 8);
    }

    float oac[2][8][4];
#pragma unroll
    for (int mt = 0; mt < 2; mt++)
#pragma unroll
        for (int j = 0; j < 8; j++)
#pragma unroll
            for (int i = 0; i < 4; i++) oac[mt][j][i] = 0.f;
    float mm[2][2], ll[2][2];
#pragma unroll
    for (int mt = 0; mt < 2; mt++) {
        mm[mt][0] = -INFINITY; mm[mt][1] = -INFINITY;
        ll[mt][0] = 0.f; ll[mt][1] = 0.f;
    }

    const int T = N_ / 64;     // 32
    for (int t = 0; t < T; t++) {
        __syncthreads();       // all warps done reading stage t-1
        if (tid == 0 && t + 1 < T) {
            int s = (t + 1) & 1;
            uint32_t mb = sbase + 8 + s * 8;
            MBAR_EXPECT_TX(mb, 32768);
            bulkcp(sQ + 32768 + s * 32768, kvblk + ((size_t)(t + 1) << 15), 32768, mb);
        }
        if (t == 0) mbar_wait(mq, 0);
        mbar_wait(sbase + 8 + (t & 1) * 8, (t >> 1) & 1);

        const uint32_t sK = sQ + 32768 + (t & 1) * 32768;
        const uint32_t sV = sK + 16384;

        // ---- S = Q @ K^T ----
        float s[2][8][4];
#pragma unroll
        for (int mt = 0; mt < 2; mt++)
#pragma unroll
            for (int j = 0; j < 8; j++)
#pragma unroll
                for (int i = 0; i < 4; i++) s[mt][j][i] = 0.f;

#pragma unroll
        for (int kt = 0; kt < 4; kt++) {
            uint32_t kfh[8][2], kfl[8][2];
#pragma unroll
            for (int jp = 0; jp < 4; jp++) {
                uint32_t r4[4];
                uint32_t rowb = jp * 16 + (lane & 7) + ((lane >> 4) << 3);
                uint32_t off = swz(rowb * 128 + kt * 32 + (((lane >> 3) & 1) << 4));
                ldsm4(r4, sK + off);
                kfh[2 * jp][0] = r4[0]; kfh[2 * jp][1] = r4[1];
                kfh[2 * jp + 1][0] = r4[2]; kfh[2 * jp + 1][1] = r4[3];
                ldsm4(r4, sK + 8192 + off);
                kfl[2 * jp][0] = r4[0]; kfl[2 * jp][1] = r4[1];
                kfl[2 * jp + 1][0] = r4[2]; kfl[2 * jp + 1][1] = r4[3];
            }
            uint32_t qf[2][4], qg[2][4];
#pragma unroll
            for (int mt = 0; mt < 2; mt++) {
                uint32_t rowa = w * 32 + mt * 16 + (lane & 15);
                uint32_t off = swz(rowa * 128 + kt * 32 + ((lane >> 4) << 4));
                ldsm4(qf[mt], sQ + off);
                ldsm4(qg[mt], sQ + 16384 + off);
            }
#pragma unroll
            for (int mt = 0; mt < 2; mt++)
#pragma unroll
                for (int j = 0; j < 8; j++)
                    mma16816(s[mt][j], qf[mt], kfh[j]);
#pragma unroll
            for (int mt = 0; mt < 2; mt++)
#pragma unroll
                for (int j = 0; j < 8; j++)
                    mma16816(s[mt][j], qf[mt], kfl[j]);
#pragma unroll
            for (int mt = 0; mt < 2; mt++)
#pragma unroll
                for (int j = 0; j < 8; j++)
                    mma16816(s[mt][j], qg[mt], kfh[j]);
        }

        // ---- online softmax ----
#pragma unroll
        for (int mt = 0; mt < 2; mt++) {
            float mx0 = -INFINITY, mx1 = -INFINITY;
#pragma unroll
            for (int j = 0; j < 8; j++) {
                mx0 = fmaxf(mx0, fmaxf(s[mt][j][0], s[mt][j][1]));
                mx1 = fmaxf(mx1, fmaxf(s[mt][j][2], s[mt][j][3]));
            }
            mx0 = fmaxf(mx0, __shfl_xor_sync(0xffffffffu, mx0, 1));
            mx0 = fmaxf(mx0, __shfl_xor_sync(0xffffffffu, mx0, 2));
            mx1 = fmaxf(mx1, __shfl_xor_sync(0xffffffffu, mx1, 1));
            mx1 = fmaxf(mx1, __shfl_xor_sync(0xffffffffu, mx1, 2));
            float mn0 = fmaxf(mm[mt][0], mx0), mn1 = fmaxf(mm[mt][1], mx1);
            float c0 = exp2f(mm[mt][0] - mn0), c1 = exp2f(mm[mt][1] - mn1);
            mm[mt][0] = mn0; mm[mt][1] = mn1;
            float rs0 = 0.f, rs1 = 0.f;
#pragma unroll
            for (int j = 0; j < 8; j++) {
                s[mt][j][0] = exp2f(s[mt][j][0] - mn0);
                s[mt][j][1] = exp2f(s[mt][j][1] - mn0);
                s[mt][j][2] = exp2f(s[mt][j][2] - mn1);
                s[mt][j][3] = exp2f(s[mt][j][3] - mn1);
                rs0 += s[mt][j][0] + s[mt][j][1];
                rs1 += s[mt][j][2] + s[mt][j][3];
            }
            rs0 += __shfl_xor_sync(0xffffffffu, rs0, 1);
            rs0 += __shfl_xor_sync(0xffffffffu, rs0, 2);
            rs1 += __shfl_xor_sync(0xffffffffu, rs1, 1);
            rs1 += __shfl_xor_sync(0xffffffffu, rs1, 2);
            ll[mt][0] = ll[mt][0] * c0 + rs0;
            ll[mt][1] = ll[mt][1] * c1 + rs1;
#pragma unroll
            for (int j = 0; j < 8; j++) {
                oac[mt][j][0] *= c0; oac[mt][j][1] *= c0;
                oac[mt][j][2] *= c1; oac[mt][j][3] *= c1;
            }
        }

        // ---- O += P @ V ----
#pragma unroll
        for (int kt2 = 0; kt2 < 4; kt2++) {
            uint32_t vfh[8][2], vfl[8][2];
#pragma unroll
            for (int hjp = 0; hjp < 4; hjp++) {
                uint32_t r4[4];
                uint32_t off = swz((kt2 * 16 + (lane & 15)) * 128 +
                                   hjp * 32 + ((lane >> 4) << 4));
                ldsm4t(r4, sV + off);
                vfh[2 * hjp][0] = r4[0]; vfh[2 * hjp][1] = r4[1];
                vfh[2 * hjp + 1][0] = r4[2]; vfh[2 * hjp + 1][1] = r4[3];
                ldsm4t(r4, sV + 8192 + off);
                vfl[2 * hjp][0] = r4[0]; vfl[2 * hjp][1] = r4[1];
                vfl[2 * hjp + 1][0] = r4[2]; vfl[2 * hjp + 1][1] = r4[3];
            }
            uint32_t pfh[2][4], pfl[2][4];
#pragma unroll
            for (int mt = 0; mt < 2; mt++) {
                split2(s[mt][2 * kt2][0],     s[mt][2 * kt2][1],     pfh[mt][0], pfl[mt][0]);
                split2(s[mt][2 * kt2][2],     s[mt][2 * kt2][3],     pfh[mt][1], pfl[mt][1]);
                split2(s[mt][2 * kt2 + 1][0], s[mt][2 * kt2 + 1][1], pfh[mt][2], pfl[mt][2]);
                split2(s[mt][2 * kt2 + 1][2], s[mt][2 * kt2 + 1][3], pfh[mt][3], pfl[mt][3]);
            }
#pragma unroll
            for (int mt = 0; mt < 2; mt++)
#pragma unroll
                for (int hj = 0; hj < 8; hj++)
                    mma16816(oac[mt][hj], pfh[mt], vfh[hj]);
#pragma unroll
            for (int mt = 0; mt < 2; mt++)
#pragma unroll
                for (int hj = 0; hj < 8; hj++)
                    mma16816(oac[mt][hj], pfh[mt], vfl[hj]);
#pragma unroll
            for (int mt = 0; mt < 2; mt++)
#pragma unroll
                for (int hj = 0; hj < 8; hj++)
                    mma16816(oac[mt][hj], pfl[mt], vfh[hj]);
        }
    }

    // ---- epilogue: normalize, split, write staged GEMM-A blocks ----
    int b = bh >> 4, h = bh & 15;
#pragma unroll
    for (int mt = 0; mt < 2; mt++) {
        float il0 = 1.0f / ll[mt][0], il1 = 1.0f / ll[mt][1];
        int r0 = b * N_ + q0 + w * 32 + mt * 16 + (lane >> 2);
#pragma unroll
        for (int hj = 0; hj < 8; hj++) {
            int c = h * 64 + hj * 8 + (lane & 3) * 2;
            int ch = c >> 5;
            uint32_t koff = (c & 31) * 2;
#pragma unroll
            for (int half = 0; half < 2; half++) {
                int rr = r0 + half * 8;
                int rb = rr >> 7, rowm = rr & 127;
                unsigned char* bo = os + ((size_t)(rb * 32 + ch) << 14);
                uint32_t off = swz64(rowm * 64 + koff);
                uint32_t hi, lo;
                if (half == 0) split2(oac[mt][hj][0] * il0, oac[mt][hj][1] * il0, hi, lo);
                else           split2(oac[mt][hj][2] * il1, oac[mt][hj][3] * il1, hi, lo);
                *(uint32_t*)(bo + off)        = hi;
                *(uint32_t*)(bo + 8192 + off) = lo;
            }
        }
    }
}

// ---------------------------------------------------------------------------
// Launch
// ---------------------------------------------------------------------------
extern "C" void kernel_launch(void* const* d_in, const int* in_sizes, int n_in,
                              void* d_out, int out_size)
{
    const float* x     = (const float*)d_in[0];
    const float* Wqkv  = (const float*)d_in[1];
    const float* qnw   = (const float*)d_in[2];
    const float* qnb   = (const float*)d_in[3];
    const float* knw   = (const float*)d_in[4];
    const float* knb   = (const float*)d_in[5];
    const float* Wproj = (const float*)d_in[6];
    const float* bproj = (const float*)d_in[7];
    float* out = (float*)d_out;

    float* qkv;
    unsigned char *xs, *wqs, *wps, *os, *qsp, *kvs;
    cudaGetSymbolAddress((void**)&qkv, g_qkv);
    cudaGetSymbolAddress((void**)&xs, g_xs);
    cudaGetSymbolAddress((void**)&wqs, g_wqs);
    cudaGetSymbolAddress((void**)&wps, g_wps);
    cudaGetSymbolAddress((void**)&os, g_os);
    cudaGetSymbolAddress((void**)&qsp, g_qs);
    cudaGetSymbolAddress((void**)&kvs, g_kvs);

    cudaFuncSetAttribute(hgemm<false>, cudaFuncAttributeMaxDynamicSharedMemorySize, HG_SMEM);
    cudaFuncSetAttribute(hgemm<true>, cudaFuncAttributeMaxDynamicSharedMemorySize, HG_SMEM);
    cudaFuncSetAttribute(attn_hmma, cudaFuncAttributeMaxDynamicSharedMemorySize, AT_SMEM);

    // 0) stage inputs & weights
    cvt_split_staged<<<M_ * 128 / 256, 256>>>(x, xs);
    cvt_transpose_split_staged<<<dim3(QKVN / 32, C_ / 32), dim3(32, 4)>>>(Wqkv, wqs, QKVN, 32);
    cvt_transpose_split_staged<<<dim3(C_ / 32, C_ / 32), dim3(32, 4)>>>(Wproj, wps, C_, 32);

    // 1) QKV GEMM
    hgemm<false><<<dim3(QKVN / 128, M_ / 128), 128, HG_SMEM>>>(xs, wqs, nullptr, qkv, QKVN, 32);

    // 2) LN + stage q/k/v
    ln_split<<<3 * M_ * H_ / 8, 256>>>(qkv, qnw, qnb, knw, knb, qsp, kvs);

    // 3) flash attention -> staged proj-A
    attn_hmma<<<dim3(N_ / 128, B_ * H_), 128, AT_SMEM>>>(qsp, kvs, os);

    // 4) proj GEMM + bias
    hgemm<true><<<dim3(C_ / 128, M_ / 128), 128, HG_SMEM>>>(os, wps, bproj, out, C_, 32);
}